// round 13
// baseline (speedup 1.0000x reference)
#include <cuda_runtime.h>
#include <cuda_fp16.h>
#include <cstdint>
#include <math.h>

#define N_TOK 8192
#define DIM   1024
#define NSEG  32            // N_TOK / 256 column segments per row

// ----------------------------- scratch -------------------------------------
__device__ __align__(256) __half g_eh[(size_t)N_TOK * DIM];
__device__ __align__(256) __half g_el[(size_t)N_TOK * DIM];
__device__ __align__(256) __half g_wqth[(size_t)DIM * DIM];
__device__ __align__(256) __half g_wqtl[(size_t)DIM * DIM];
__device__ __align__(256) __half g_wkth[(size_t)DIM * DIM];
__device__ __align__(256) __half g_wktl[(size_t)DIM * DIM];
__device__ __align__(256) __half g_wvh[(size_t)DIM * DIM];
__device__ __align__(256) float  g_mtp[(size_t)4 * DIM * DIM];
__device__ __align__(256) __half g_mth[(size_t)DIM * DIM];
__device__ __align__(256) __half g_mtl[(size_t)DIM * DIM];
__device__ __align__(256) __half g_th[(size_t)N_TOK * DIM];
__device__ __align__(256) __half g_tl[(size_t)N_TOK * DIM];
__device__ __align__(256) float  g_b2[DIM];
__device__ __align__(256) float  g_beta[N_TOK];
__device__ __align__(256) __half g_s16[(size_t)N_TOK * N_TOK];
__device__ __align__(256) float  g_smax[(size_t)N_TOK * NSEG];
__device__ __align__(256) __half g_gh[(size_t)N_TOK * DIM];

// ----------------------------- helpers -------------------------------------
__device__ __forceinline__ uint32_t smem_u32(const void* p) {
    uint32_t a;
    asm("{ .reg .u64 t; cvta.to.shared.u64 t, %1; cvt.u32.u64 %0, t; }" : "=r"(a) : "l"(p));
    return a;
}
__device__ __forceinline__ void cp16(uint32_t dst, const void* src) {
    asm volatile("cp.async.cg.shared.global [%0], [%1], 16;" :: "r"(dst), "l"(src));
}
__device__ __forceinline__ void cp_commit() { asm volatile("cp.async.commit_group;" ::: "memory"); }
template <int N> __device__ __forceinline__ void cp_wait() {
    asm volatile("cp.async.wait_group %0;" :: "n"(N) : "memory");
}
#define LDSM4(r, addr) \
    asm volatile("ldmatrix.sync.aligned.m8n8.x4.shared.b16 {%0,%1,%2,%3}, [%4];" \
                 : "=r"((r)[0]), "=r"((r)[1]), "=r"((r)[2]), "=r"((r)[3]) : "r"(addr))
#define MMA16816(c, a, b0, b1) \
    asm volatile("mma.sync.aligned.m16n8k16.row.col.f32.f16.f16.f32 " \
                 "{%0,%1,%2,%3},{%4,%5,%6,%7},{%8,%9},{%0,%1,%2,%3};" \
                 : "+f"((c)[0]), "+f"((c)[1]), "+f"((c)[2]), "+f"((c)[3]) \
                 : "r"((a)[0]), "r"((a)[1]), "r"((a)[2]), "r"((a)[3]), "r"(b0), "r"(b1))

// ----------------------------- wide split GEMM ------------------------------
// C[M,N] = A[M,K]@B[N,K]^T (+bias); A/B fp16 hi(+lo) limb pairs.
// NPASS 3: hh + hl + lh (fp32 acc).  NPASS 1: hh only.
// outMode: 0 f32, 1 fp16 hi+lo, 2 fp16 hi (+ optional per-row-segment max).
#define KC 32
#define ROWP 80
#define A_H 0
#define A_L (128 * ROWP)
#define B_H (2 * 128 * ROWP)
#define B_L (B_H + 256 * ROWP)
#define STAGE (B_L + 256 * ROWP)
#define GSMEM (2 * STAGE)

template <int NPASS>
__global__ __launch_bounds__(256, 1)
void gemm_w(const __half* __restrict__ Ah, const __half* __restrict__ Al, int lda,
            const __half* __restrict__ Bh, const __half* __restrict__ Bl, int ldb,
            const float* __restrict__ bias, int biasMode,
            float* __restrict__ Cf, __half* __restrict__ Ch, __half* __restrict__ Cl,
            float* __restrict__ segMax,
            int ldc, int K, int outMode, long long zStride)
{
    extern __shared__ char smem[];
    const uint32_t sb = smem_u32(smem);
    const int t = threadIdx.x, lane = t & 31, wid = t >> 5;
    const int wm = wid >> 2, wn = wid & 3;
    const int m0 = blockIdx.y * 128, n0 = blockIdx.x * 256;
    const size_t kz = (size_t)blockIdx.z * (size_t)K;
    const int S = K / KC;

    auto load_stage = [&](int s, int buf) {
        const size_t kt = kz + (size_t)s * KC;
        const uint32_t base = sb + (uint32_t)buf * STAGE;
#pragma unroll
        for (int i = 0; i < 2; i++) {
            const int cid = i * 256 + t;
            const int row = cid >> 2, ch = cid & 3;
            const uint32_t off = row * ROWP + ch * 16;
            const size_t g = (size_t)(m0 + row) * lda + kt + ch * 8;
            cp16(base + A_H + off, Ah + g);
            if (NPASS == 3) cp16(base + A_L + off, Al + g);
        }
#pragma unroll
        for (int i = 0; i < 4; i++) {
            const int cid = i * 256 + t;
            const int row = cid >> 2, ch = cid & 3;
            const uint32_t off = row * ROWP + ch * 16;
            const size_t g = (size_t)(n0 + row) * ldb + kt + ch * 8;
            cp16(base + B_H + off, Bh + g);
            if (NPASS == 3) cp16(base + B_L + off, Bl + g);
        }
        cp_commit();
    };

    float c[4][8][4];
#pragma unroll
    for (int i = 0; i < 4; i++)
#pragma unroll
        for (int j = 0; j < 8; j++)
#pragma unroll
            for (int q = 0; q < 4; q++) c[i][j][q] = 0.0f;

    load_stage(0, 0);
    load_stage(1, 1);

    const uint32_t aoff = (uint32_t)(wm * 64 + (lane & 15)) * ROWP + (uint32_t)((lane >> 4) * 16);
    const uint32_t boff = (uint32_t)(wn * 64 + (lane & 15)) * ROWP + (uint32_t)((lane >> 4) * 16);

    for (int s = 0; s < S; s++) {
        if (s < S - 1) cp_wait<1>(); else cp_wait<0>();
        __syncthreads();
        const uint32_t base = sb + (uint32_t)(s & 1) * STAGE;

#pragma unroll
        for (int kh = 0; kh < 2; kh++) {
            const uint32_t kb = (uint32_t)(kh * 32);
            uint32_t ah[4][4], bx[4][4];
#pragma unroll
            for (int mi = 0; mi < 4; mi++)
                LDSM4(ah[mi], base + A_H + aoff + (uint32_t)(mi * 16 * ROWP) + kb);
#pragma unroll
            for (int g = 0; g < 4; g++)
                LDSM4(bx[g], base + B_H + boff + (uint32_t)(g * 16 * ROWP) + kb);
#pragma unroll
            for (int mi = 0; mi < 4; mi++)
#pragma unroll
                for (int g = 0; g < 4; g++) {
                    MMA16816(c[mi][2 * g],     ah[mi], bx[g][0], bx[g][2]);
                    MMA16816(c[mi][2 * g + 1], ah[mi], bx[g][1], bx[g][3]);
                }
            if (NPASS == 3) {
                {
                    uint32_t bl[4][4];
#pragma unroll
                    for (int g = 0; g < 4; g++)
                        LDSM4(bl[g], base + B_L + boff + (uint32_t)(g * 16 * ROWP) + kb);
#pragma unroll
                    for (int mi = 0; mi < 4; mi++)
#pragma unroll
                        for (int g = 0; g < 4; g++) {
                            MMA16816(c[mi][2 * g],     ah[mi], bl[g][0], bl[g][2]);
                            MMA16816(c[mi][2 * g + 1], ah[mi], bl[g][1], bl[g][3]);
                        }
                }
                {
                    uint32_t al[4][4];
#pragma unroll
                    for (int mi = 0; mi < 4; mi++)
                        LDSM4(al[mi], base + A_L + aoff + (uint32_t)(mi * 16 * ROWP) + kb);
#pragma unroll
                    for (int mi = 0; mi < 4; mi++)
#pragma unroll
                        for (int g = 0; g < 4; g++) {
                            MMA16816(c[mi][2 * g],     al[mi], bx[g][0], bx[g][2]);
                            MMA16816(c[mi][2 * g + 1], al[mi], bx[g][1], bx[g][3]);
                        }
                }
            }
        }
        __syncthreads();
        if (s + 2 < S) load_stage(s + 2, s & 1);
    }

    float* Cfz = Cf + (size_t)blockIdx.z * (size_t)zStride;
    const int rbase = m0 + wm * 64 + (lane >> 2);
    const int cbase = n0 + wn * 64 + (lane & 3) * 2;
    float rmax8[8];
#pragma unroll
    for (int i = 0; i < 8; i++) rmax8[i] = -1e30f;

#pragma unroll
    for (int mi = 0; mi < 4; mi++) {
#pragma unroll
        for (int nj = 0; nj < 8; nj++) {
            const int col = cbase + nj * 8;
            float bc0 = 0.0f, bc1 = 0.0f;
            if (biasMode == 1) { bc0 = bias[col]; bc1 = bias[col + 1]; }
#pragma unroll
            for (int h = 0; h < 2; h++) {
                const int row = rbase + mi * 16 + h * 8;
                float v0 = c[mi][nj][2 * h + 0] + bc0;
                float v1 = c[mi][nj][2 * h + 1] + bc1;
                if (biasMode == 2) { const float br = bias[row]; v0 += br; v1 += br; }
                const size_t off = (size_t)row * ldc + col;
                if (outMode == 0) {
                    *(float2*)(Cfz + off) = make_float2(v0, v1);
                } else {
                    const __half h0 = __float2half(v0), h1 = __float2half(v1);
                    __half2 hp = __halves2half2(h0, h1);
                    *(uint32_t*)(Ch + off) = *(uint32_t*)&hp;
                    if (outMode == 1) {
                        const __half l0 = __float2half(v0 - __half2float(h0));
                        const __half l1 = __float2half(v1 - __half2float(h1));
                        __half2 lp = __halves2half2(l0, l1);
                        *(uint32_t*)(Cl + off) = *(uint32_t*)&lp;
                    }
                    rmax8[mi * 2 + h] = fmaxf(rmax8[mi * 2 + h], fmaxf(v0, v1));
                }
            }
        }
    }

    // per-row segment max (scores GEMM only): reduce 16 partials/row in smem
    if (outMode == 2 && segMax) {
        __syncthreads();                     // mainloop smem no longer needed
        float* rbuf = (float*)smem;          // [128][16]
        const int slot = wn * 4 + (lane & 3);
#pragma unroll
        for (int mi = 0; mi < 4; mi++)
#pragma unroll
            for (int h = 0; h < 2; h++) {
                const int rl = wm * 64 + (lane >> 2) + mi * 16 + h * 8;
                rbuf[rl * 16 + slot] = rmax8[mi * 2 + h];
            }
        __syncthreads();
        if (t < 128) {
            float m = rbuf[t * 16];
#pragma unroll
            for (int i = 1; i < 16; i++) m = fmaxf(m, rbuf[t * 16 + i]);
            segMax[(size_t)(m0 + t) * gridDim.x + blockIdx.x] = m;
        }
    }
}

// ----------------------------- elementwise split ---------------------------
__global__ __launch_bounds__(256)
void split_f32(const float* __restrict__ x, __half* __restrict__ h,
               __half* __restrict__ l, int n4)
{
    int i = blockIdx.x * 256 + threadIdx.x;
    if (i >= n4) return;
    float4 v = ((const float4*)x)[i];
    __half h0 = __float2half(v.x), h1 = __float2half(v.y);
    __half h2 = __float2half(v.z), h3 = __float2half(v.w);
    __half2 a = __halves2half2(h0, h1), b = __halves2half2(h2, h3);
    if (l) {
        __half2 cc = __halves2half2(__float2half(v.x - __half2float(h0)), __float2half(v.y - __half2float(h1)));
        __half2 d = __halves2half2(__float2half(v.z - __half2float(h2)), __float2half(v.w - __half2float(h3)));
        ((uint2*)l)[i] = make_uint2(*(uint32_t*)&cc, *(uint32_t*)&d);
    }
    ((uint2*)h)[i] = make_uint2(*(uint32_t*)&a, *(uint32_t*)&b);
}

// ----------------------------- transpose + split (2 matrices via z) ---------
__global__ __launch_bounds__(256)
void transpose_split2(const float* __restrict__ x0, __half* __restrict__ h0p, __half* __restrict__ l0p,
                      const float* __restrict__ x1, __half* __restrict__ h1p, __half* __restrict__ l1p,
                      int R, int C)
{
    const float* x = blockIdx.z ? x1 : x0;
    __half* h = blockIdx.z ? h1p : h0p;
    __half* l = blockIdx.z ? l1p : l0p;
    __shared__ float tile[32][33];
    const int c0 = blockIdx.x * 32, r0 = blockIdx.y * 32;
    const int tx = threadIdx.x & 31, ty = threadIdx.x >> 5;
#pragma unroll
    for (int i = 0; i < 32; i += 8)
        tile[ty + i][tx] = x[(size_t)(r0 + ty + i) * C + c0 + tx];
    __syncthreads();
#pragma unroll
    for (int i = 0; i < 32; i += 8) {
        const int c = c0 + ty + i, r = r0 + tx;
        const float v = tile[tx][ty + i];
        const __half hv = __float2half(v);
        h[(size_t)c * R + r] = hv;
        l[(size_t)c * R + r] = __float2half(v - __half2float(hv));
    }
}

// ----------------------------- reduce split-K partials ----------------------
__global__ __launch_bounds__(256)
void reduce4_split(const float* __restrict__ p, __half* __restrict__ h,
                   __half* __restrict__ l, int n)
{
    int i = blockIdx.x * 256 + threadIdx.x;
    if (i >= n) return;
    float v = p[i] + p[i + n] + p[i + 2 * n] + p[i + 3 * n];
    __half hv = __float2half(v);
    h[i] = hv;
    l[i] = __float2half(v - __half2float(hv));
}

// ----------------------------- bias-fold GEMVs ------------------------------
__global__ __launch_bounds__(256)
void bvec_k(const float* __restrict__ Wk, const float* __restrict__ bq,
            float* __restrict__ b2)
{
    const int b = blockIdx.x * 256 + threadIdx.x;
    float s = 0.0f;
    for (int o = 0; o < DIM; o++) s += Wk[(size_t)o * DIM + b] * bq[o];
    b2[b] = s;
}
__global__ __launch_bounds__(256)
void beta_k(const float* __restrict__ E, const float* __restrict__ b2,
            float* __restrict__ beta)
{
    const int row = blockIdx.x * 8 + (threadIdx.x >> 5);
    const int lane = threadIdx.x & 31;
    const float* e = E + (size_t)row * DIM;
    float s = 0.0f;
    for (int b = lane; b < DIM; b += 32) s += e[b] * b2[b];
#pragma unroll
    for (int o = 16; o > 0; o >>= 1) s += __shfl_xor_sync(~0u, s, o);
    if (lane == 0) beta[row] = s;
}

// ------- fused select (segment-screened) + exact rescore + gather -> G ------
// Segment maxes (from the scores-GEMM epilogue) give the row max directly;
// only segments with segmax > thr are scanned (typically 1-2 of 32).
// Candidate order is ascending column (deterministic).
#define MARGIN 22.0f
#define MAXC 512
__global__ __launch_bounds__(256)
void select_refine_gather(const __half* __restrict__ St, const float* __restrict__ segMax,
                          const __half* __restrict__ Th, const __half* __restrict__ Tl,
                          const float* __restrict__ beta, const float* __restrict__ E,
                          __half* __restrict__ Gh)
{
    const size_t row = blockIdx.x;
    const int t = threadIdx.x, lane = t & 31, warp = t >> 5;

    __shared__ float tf[DIM];
    __shared__ float smaxsh[NSEG];
    __shared__ float thr_sh;
    __shared__ int   wtot[8];
    __shared__ int   cols[MAXC];
    __shared__ float sc[MAXC];
    __shared__ int   Lsh;

    for (int i = t; i < DIM; i += 256)
        tf[i] = __half2float(Th[row * DIM + i]) + __half2float(Tl[row * DIM + i]);
    if (t < NSEG) smaxsh[t] = segMax[row * NSEG + t];
    if (t == 0) Lsh = 0;
    __syncthreads();
    if (t == 0) {
        float m = smaxsh[0];
#pragma unroll
        for (int i = 1; i < NSEG; i++) m = fmaxf(m, smaxsh[i]);
        thr_sh = m - MARGIN;
    }
    __syncthreads();
    const float thr = thr_sh;

    // candidate collection over passing segments (deterministic, ascending col)
    for (int seg = 0; seg < NSEG; seg++) {
        if (smaxsh[seg] <= thr) continue;
        const int col = seg * 256 + t;
        const float s = __half2float(St[row * N_TOK + col]);
        const int pred = (s > thr);
        const unsigned m = __ballot_sync(~0u, pred);
        if (lane == 0) wtot[warp] = __popc(m);
        __syncthreads();
        int base = Lsh, wb = 0;
#pragma unroll
        for (int w = 0; w < 8; w++) if (w < warp) wb += wtot[w];
        const int idx = base + wb + __popc(m & ((1u << lane) - 1u));
        if (pred && idx < MAXC) cols[idx] = col;
        __syncthreads();
        if (t == 0) {
            int tot = 0;
#pragma unroll
            for (int w = 0; w < 8; w++) tot += wtot[w];
            Lsh = min(base + tot, MAXC);
        }
        __syncthreads();
    }
    const int L = Lsh;

    // exact re-score: one warp per candidate
    for (int ci = warp; ci < L; ci += 8) {
        const int j = cols[ci];
        const float* ej = E + (size_t)j * DIM;
        float s = 0.0f;
        for (int k = lane; k < DIM; k += 32) s += tf[k] * ej[k];
#pragma unroll
        for (int o = 16; o > 0; o >>= 1) s += __shfl_xor_sync(~0u, s, o);
        if (lane == 0) sc[ci] = s + beta[j];
    }
    __syncthreads();

    float m2 = -1e30f;
    for (int i = 0; i < L; i++) m2 = fmaxf(m2, sc[i]);
    float sum = 0.0f;
    for (int i = 0; i < L; i++) sum += __expf(sc[i] - m2);
    const float inv = 1.0f / sum;

    float4 acc = make_float4(0.f, 0.f, 0.f, 0.f);
    for (int i = 0; i < L; i++) {
        const float p = __expf(sc[i] - m2) * inv;
        const float4 e = ((const float4*)(E + (size_t)cols[i] * DIM))[t];
        acc.x += p * e.x; acc.y += p * e.y;
        acc.z += p * e.z; acc.w += p * e.w;
    }
    __half2 g0 = __halves2half2(__float2half(acc.x), __float2half(acc.y));
    __half2 g1 = __halves2half2(__float2half(acc.z), __float2half(acc.w));
    ((uint2*)(Gh + row * DIM))[t] = make_uint2(*(uint32_t*)&g0, *(uint32_t*)&g1);
}

// ----------------------------- launch --------------------------------------
extern "C" void kernel_launch(void* const* d_in, const int* in_sizes, int n_in,
                              void* d_out, int out_size)
{
    const float* emb = (const float*)d_in[0];
    const float* Wq  = (const float*)d_in[1];
    const float* bq  = (const float*)d_in[2];
    const float* Wk  = (const float*)d_in[3];
    const float* bk  = (const float*)d_in[4];   // cancels in softmax (row-const)
    const float* Wv  = (const float*)d_in[5];
    const float* bv  = (const float*)d_in[6];
    float* out = (float*)d_out;
    (void)bk;

    __half *eh, *el, *wqth, *wqtl, *wkth, *wktl, *wvh;
    __half *mth, *mtl, *th, *tl, *s16, *gh;
    float *mtp, *b2, *betav, *smax;
    cudaGetSymbolAddress((void**)&eh, g_eh);     cudaGetSymbolAddress((void**)&el, g_el);
    cudaGetSymbolAddress((void**)&wqth, g_wqth); cudaGetSymbolAddress((void**)&wqtl, g_wqtl);
    cudaGetSymbolAddress((void**)&wkth, g_wkth); cudaGetSymbolAddress((void**)&wktl, g_wktl);
    cudaGetSymbolAddress((void**)&wvh, g_wvh);
    cudaGetSymbolAddress((void**)&mtp, g_mtp);
    cudaGetSymbolAddress((void**)&mth, g_mth);   cudaGetSymbolAddress((void**)&mtl, g_mtl);
    cudaGetSymbolAddress((void**)&th, g_th);     cudaGetSymbolAddress((void**)&tl, g_tl);
    cudaGetSymbolAddress((void**)&b2, g_b2);     cudaGetSymbolAddress((void**)&betav, g_beta);
    cudaGetSymbolAddress((void**)&s16, g_s16);   cudaGetSymbolAddress((void**)&smax, g_smax);
    cudaGetSymbolAddress((void**)&gh, g_gh);

    static int once = 0;
    if (!once) {
        cudaFuncSetAttribute(gemm_w<3>, cudaFuncAttributeMaxDynamicSharedMemorySize, GSMEM);
        cudaFuncSetAttribute(gemm_w<1>, cudaFuncAttributeMaxDynamicSharedMemorySize, GSMEM);
        once = 1;
    }

    // preps
    split_f32<<<N_TOK * DIM / 4 / 256, 256>>>(emb, eh, el, N_TOK * DIM / 4);
    transpose_split2<<<dim3(DIM / 32, DIM / 32, 2), 256>>>(Wq, wqth, wqtl, Wk, wkth, wktl, DIM, DIM);
    split_f32<<<DIM * DIM / 4 / 256, 256>>>(Wv, wvh, nullptr, DIM * DIM / 4);
    bvec_k<<<DIM / 256, 256>>>(Wk, bq, b2);
    beta_k<<<N_TOK / 8, 256>>>(emb, b2, betav);

    // M^T = Wk^T @ Wq  (split-K z=4)
    gemm_w<3><<<dim3(DIM / 256, DIM / 128, 4), 256, GSMEM>>>(
        wkth, wktl, DIM, wqth, wqtl, DIM, nullptr, 0,
        mtp, nullptr, nullptr, nullptr, DIM, DIM / 4, 0, (long long)DIM * DIM);
    reduce4_split<<<DIM * DIM / 256, 256>>>(mtp, mth, mtl, DIM * DIM);

    // T = E @ M  -> split hi/lo
    gemm_w<3><<<dim3(DIM / 256, N_TOK / 128), 256, GSMEM>>>(
        eh, el, DIM, mth, mtl, DIM, nullptr, 0,
        nullptr, th, tl, nullptr, DIM, DIM, 1, 0);

    // approx scores: S~ = Th @ Eh^T + beta(col), fp16 + per-segment row maxes
    gemm_w<1><<<dim3(N_TOK / 256, N_TOK / 128), 256, GSMEM>>>(
        th, nullptr, DIM, eh, nullptr, DIM, betav, 1,
        nullptr, s16, nullptr, smax, N_TOK, DIM, 2, 0);

    // segment-screened select + exact rescore + softmax + sparse P*E -> G
    select_refine_gather<<<N_TOK, 256>>>(s16, smax, th, tl, betav, emb, gh);

    // out = G @ Wv^T + bv  (1-pass)
    gemm_w<1><<<dim3(DIM / 256, N_TOK / 128), 256, GSMEM>>>(
        gh, nullptr, DIM, wvh, nullptr, DIM, bv, 1,
        out, nullptr, nullptr, nullptr, DIM, DIM, 0, 0);
}

// round 14
// speedup vs baseline: 1.0589x; 1.0589x over previous
#include <cuda_runtime.h>
#include <cuda_fp16.h>
#include <cstdint>
#include <math.h>

#define N_TOK 8192
#define DIM   1024

// ----------------------------- scratch -------------------------------------
__device__ __align__(256) __half g_eh[(size_t)N_TOK * DIM];
__device__ __align__(256) __half g_el[(size_t)N_TOK * DIM];
__device__ __align__(256) __half g_wqth[(size_t)DIM * DIM];
__device__ __align__(256) __half g_wqtl[(size_t)DIM * DIM];
__device__ __align__(256) __half g_wkth[(size_t)DIM * DIM];
__device__ __align__(256) __half g_wktl[(size_t)DIM * DIM];
__device__ __align__(256) __half g_wvh[(size_t)DIM * DIM];
__device__ __align__(256) float  g_mtp[(size_t)4 * DIM * DIM];
__device__ __align__(256) __half g_mth[(size_t)DIM * DIM];
__device__ __align__(256) __half g_mtl[(size_t)DIM * DIM];
__device__ __align__(256) __half g_th[(size_t)N_TOK * DIM];
__device__ __align__(256) __half g_tl[(size_t)N_TOK * DIM];
__device__ __align__(256) float  g_b2[DIM];
__device__ __align__(256) float  g_beta[N_TOK];
__device__ __align__(256) __half g_s16[(size_t)N_TOK * N_TOK];
__device__ __align__(256) __half g_gh[(size_t)N_TOK * DIM];

// ----------------------------- helpers -------------------------------------
__device__ __forceinline__ uint32_t smem_u32(const void* p) {
    uint32_t a;
    asm("{ .reg .u64 t; cvta.to.shared.u64 t, %1; cvt.u32.u64 %0, t; }" : "=r"(a) : "l"(p));
    return a;
}
__device__ __forceinline__ void cp16(uint32_t dst, const void* src) {
    asm volatile("cp.async.cg.shared.global [%0], [%1], 16;" :: "r"(dst), "l"(src));
}
__device__ __forceinline__ void cp_commit() { asm volatile("cp.async.commit_group;" ::: "memory"); }
template <int N> __device__ __forceinline__ void cp_wait() {
    asm volatile("cp.async.wait_group %0;" :: "n"(N) : "memory");
}
#define LDSM4(r, addr) \
    asm volatile("ldmatrix.sync.aligned.m8n8.x4.shared.b16 {%0,%1,%2,%3}, [%4];" \
                 : "=r"((r)[0]), "=r"((r)[1]), "=r"((r)[2]), "=r"((r)[3]) : "r"(addr))
#define MMA16816(c, a, b0, b1) \
    asm volatile("mma.sync.aligned.m16n8k16.row.col.f32.f16.f16.f32 " \
                 "{%0,%1,%2,%3},{%4,%5,%6,%7},{%8,%9},{%0,%1,%2,%3};" \
                 : "+f"((c)[0]), "+f"((c)[1]), "+f"((c)[2]), "+f"((c)[3]) \
                 : "r"((a)[0]), "r"((a)[1]), "r"((a)[2]), "r"((a)[3]), "r"(b0), "r"(b1))

// ----------------------------- wide split GEMM ------------------------------
// C[M,N] = A[M,K]@B[N,K]^T (+bias); A/B fp16 hi(+lo) limb pairs.
// NPASS 3: hh + hl + lh (fp32 acc).  NPASS 1: hh only.
// CTA tile 128x256, kc=32, 2-stage cp.async, 8 warps (2m x 4n), warp 64x64.
// biasMode: 0 none, 1 per-col, 2 per-row. outMode: 0 f32, 1 fp16 hi+lo, 2 fp16 hi.
#define KC 32
#define ROWP 80
#define A_H 0
#define A_L (128 * ROWP)
#define B_H (2 * 128 * ROWP)
#define B_L (B_H + 256 * ROWP)
#define STAGE (B_L + 256 * ROWP)
#define GSMEM (2 * STAGE)

template <int NPASS>
__global__ __launch_bounds__(256, 1)
void gemm_w(const __half* __restrict__ Ah, const __half* __restrict__ Al, int lda,
            const __half* __restrict__ Bh, const __half* __restrict__ Bl, int ldb,
            const float* __restrict__ bias, int biasMode,
            float* __restrict__ Cf, __half* __restrict__ Ch, __half* __restrict__ Cl,
            int ldc, int K, int outMode, long long zStride)
{
    extern __shared__ char smem[];
    const uint32_t sb = smem_u32(smem);
    const int t = threadIdx.x, lane = t & 31, wid = t >> 5;
    const int wm = wid >> 2, wn = wid & 3;
    const int m0 = blockIdx.y * 128, n0 = blockIdx.x * 256;
    const size_t kz = (size_t)blockIdx.z * (size_t)K;
    const int S = K / KC;

    auto load_stage = [&](int s, int buf) {
        const size_t kt = kz + (size_t)s * KC;
        const uint32_t base = sb + (uint32_t)buf * STAGE;
#pragma unroll
        for (int i = 0; i < 2; i++) {
            const int cid = i * 256 + t;
            const int row = cid >> 2, ch = cid & 3;
            const uint32_t off = row * ROWP + ch * 16;
            const size_t g = (size_t)(m0 + row) * lda + kt + ch * 8;
            cp16(base + A_H + off, Ah + g);
            if (NPASS == 3) cp16(base + A_L + off, Al + g);
        }
#pragma unroll
        for (int i = 0; i < 4; i++) {
            const int cid = i * 256 + t;
            const int row = cid >> 2, ch = cid & 3;
            const uint32_t off = row * ROWP + ch * 16;
            const size_t g = (size_t)(n0 + row) * ldb + kt + ch * 8;
            cp16(base + B_H + off, Bh + g);
            if (NPASS == 3) cp16(base + B_L + off, Bl + g);
        }
        cp_commit();
    };

    float c[4][8][4];
#pragma unroll
    for (int i = 0; i < 4; i++)
#pragma unroll
        for (int j = 0; j < 8; j++)
#pragma unroll
            for (int q = 0; q < 4; q++) c[i][j][q] = 0.0f;

    load_stage(0, 0);
    load_stage(1, 1);

    const uint32_t aoff = (uint32_t)(wm * 64 + (lane & 15)) * ROWP + (uint32_t)((lane >> 4) * 16);
    const uint32_t boff = (uint32_t)(wn * 64 + (lane & 15)) * ROWP + (uint32_t)((lane >> 4) * 16);

    for (int s = 0; s < S; s++) {
        if (s < S - 1) cp_wait<1>(); else cp_wait<0>();
        __syncthreads();
        const uint32_t base = sb + (uint32_t)(s & 1) * STAGE;

#pragma unroll
        for (int kh = 0; kh < 2; kh++) {
            const uint32_t kb = (uint32_t)(kh * 32);
            uint32_t ah[4][4], bx[4][4];
#pragma unroll
            for (int mi = 0; mi < 4; mi++)
                LDSM4(ah[mi], base + A_H + aoff + (uint32_t)(mi * 16 * ROWP) + kb);
#pragma unroll
            for (int g = 0; g < 4; g++)
                LDSM4(bx[g], base + B_H + boff + (uint32_t)(g * 16 * ROWP) + kb);
#pragma unroll
            for (int mi = 0; mi < 4; mi++)
#pragma unroll
                for (int g = 0; g < 4; g++) {
                    MMA16816(c[mi][2 * g],     ah[mi], bx[g][0], bx[g][2]);
                    MMA16816(c[mi][2 * g + 1], ah[mi], bx[g][1], bx[g][3]);
                }
            if (NPASS == 3) {
                {
                    uint32_t bl[4][4];
#pragma unroll
                    for (int g = 0; g < 4; g++)
                        LDSM4(bl[g], base + B_L + boff + (uint32_t)(g * 16 * ROWP) + kb);
#pragma unroll
                    for (int mi = 0; mi < 4; mi++)
#pragma unroll
                        for (int g = 0; g < 4; g++) {
                            MMA16816(c[mi][2 * g],     ah[mi], bl[g][0], bl[g][2]);
                            MMA16816(c[mi][2 * g + 1], ah[mi], bl[g][1], bl[g][3]);
                        }
                }
                {
                    uint32_t al[4][4];
#pragma unroll
                    for (int mi = 0; mi < 4; mi++)
                        LDSM4(al[mi], base + A_L + aoff + (uint32_t)(mi * 16 * ROWP) + kb);
#pragma unroll
                    for (int mi = 0; mi < 4; mi++)
#pragma unroll
                        for (int g = 0; g < 4; g++) {
                            MMA16816(c[mi][2 * g],     al[mi], bx[g][0], bx[g][2]);
                            MMA16816(c[mi][2 * g + 1], al[mi], bx[g][1], bx[g][3]);
                        }
                }
            }
        }
        __syncthreads();
        if (s + 2 < S) load_stage(s + 2, s & 1);
    }

    float* Cfz = Cf + (size_t)blockIdx.z * (size_t)zStride;
    const int rbase = m0 + wm * 64 + (lane >> 2);
    const int cbase = n0 + wn * 64 + (lane & 3) * 2;
#pragma unroll
    for (int mi = 0; mi < 4; mi++) {
#pragma unroll
        for (int nj = 0; nj < 8; nj++) {
            const int col = cbase + nj * 8;
            float bc0 = 0.0f, bc1 = 0.0f;
            if (biasMode == 1) { bc0 = bias[col]; bc1 = bias[col + 1]; }
#pragma unroll
            for (int h = 0; h < 2; h++) {
                const int row = rbase + mi * 16 + h * 8;
                float v0 = c[mi][nj][2 * h + 0] + bc0;
                float v1 = c[mi][nj][2 * h + 1] + bc1;
                if (biasMode == 2) { const float br = bias[row]; v0 += br; v1 += br; }
                const size_t off = (size_t)row * ldc + col;
                if (outMode == 0) {
                    *(float2*)(Cfz + off) = make_float2(v0, v1);
                } else {
                    const __half h0 = __float2half(v0), h1 = __float2half(v1);
                    __half2 hp = __halves2half2(h0, h1);
                    *(uint32_t*)(Ch + off) = *(uint32_t*)&hp;
                    if (outMode == 1) {
                        const __half l0 = __float2half(v0 - __half2float(h0));
                        const __half l1 = __float2half(v1 - __half2float(h1));
                        __half2 lp = __halves2half2(l0, l1);
                        *(uint32_t*)(Cl + off) = *(uint32_t*)&lp;
                    }
                }
            }
        }
    }
}

// ----------------------------- elementwise split ---------------------------
__global__ __launch_bounds__(256)
void split_f32(const float* __restrict__ x, __half* __restrict__ h,
               __half* __restrict__ l, int n4)
{
    int i = blockIdx.x * 256 + threadIdx.x;
    if (i >= n4) return;
    float4 v = ((const float4*)x)[i];
    __half h0 = __float2half(v.x), h1 = __float2half(v.y);
    __half h2 = __float2half(v.z), h3 = __float2half(v.w);
    __half2 a = __halves2half2(h0, h1), b = __halves2half2(h2, h3);
    if (l) {
        __half2 cc = __halves2half2(__float2half(v.x - __half2float(h0)), __float2half(v.y - __half2float(h1)));
        __half2 d = __halves2half2(__float2half(v.z - __half2float(h2)), __float2half(v.w - __half2float(h3)));
        ((uint2*)l)[i] = make_uint2(*(uint32_t*)&cc, *(uint32_t*)&d);
    }
    ((uint2*)h)[i] = make_uint2(*(uint32_t*)&a, *(uint32_t*)&b);
}

// ----------------------------- transpose + split (2 matrices via z) ---------
__global__ __launch_bounds__(256)
void transpose_split2(const float* __restrict__ x0, __half* __restrict__ h0p, __half* __restrict__ l0p,
                      const float* __restrict__ x1, __half* __restrict__ h1p, __half* __restrict__ l1p,
                      int R, int C)
{
    const float* x = blockIdx.z ? x1 : x0;
    __half* h = blockIdx.z ? h1p : h0p;
    __half* l = blockIdx.z ? l1p : l0p;
    __shared__ float tile[32][33];
    const int c0 = blockIdx.x * 32, r0 = blockIdx.y * 32;
    const int tx = threadIdx.x & 31, ty = threadIdx.x >> 5;
#pragma unroll
    for (int i = 0; i < 32; i += 8)
        tile[ty + i][tx] = x[(size_t)(r0 + ty + i) * C + c0 + tx];
    __syncthreads();
#pragma unroll
    for (int i = 0; i < 32; i += 8) {
        const int c = c0 + ty + i, r = r0 + tx;
        const float v = tile[tx][ty + i];
        const __half hv = __float2half(v);
        h[(size_t)c * R + r] = hv;
        l[(size_t)c * R + r] = __float2half(v - __half2float(hv));
    }
}

// ----------------------------- reduce split-K partials ----------------------
__global__ __launch_bounds__(256)
void reduce4_split(const float* __restrict__ p, __half* __restrict__ h,
                   __half* __restrict__ l, int n)
{
    int i = blockIdx.x * 256 + threadIdx.x;
    if (i >= n) return;
    float v = p[i] + p[i + n] + p[i + 2 * n] + p[i + 3 * n];
    __half hv = __float2half(v);
    h[i] = hv;
    l[i] = __float2half(v - __half2float(hv));
}

// ----------------------------- bias-fold GEMVs ------------------------------
// b2[b] = sum_o Wk[o,b]*bq[o] = (WkT row b) . bq, using fp16 hi/lo limbs of WkT
// (reconstruction exact to 2^-22). Warp per output: coalesced row reads.
__global__ __launch_bounds__(256)
void bvec_k(const __half* __restrict__ WkTh, const __half* __restrict__ WkTl,
            const float* __restrict__ bq, float* __restrict__ b2)
{
    const int b = blockIdx.x * 8 + (threadIdx.x >> 5);
    const int lane = threadIdx.x & 31;
    const __half* rh = WkTh + (size_t)b * DIM;
    const __half* rl = WkTl + (size_t)b * DIM;
    float s = 0.0f;
    for (int o = lane; o < DIM; o += 32)
        s += (__half2float(rh[o]) + __half2float(rl[o])) * bq[o];
#pragma unroll
    for (int o = 16; o > 0; o >>= 1) s += __shfl_xor_sync(~0u, s, o);
    if (lane == 0) b2[b] = s;
}
__global__ __launch_bounds__(256)
void beta_k(const float* __restrict__ E, const float* __restrict__ b2,
            float* __restrict__ beta)
{
    const int row = blockIdx.x * 8 + (threadIdx.x >> 5);
    const int lane = threadIdx.x & 31;
    const float* e = E + (size_t)row * DIM;
    float s = 0.0f;
    for (int b = lane; b < DIM; b += 32) s += e[b] * b2[b];
#pragma unroll
    for (int o = 16; o > 0; o >>= 1) s += __shfl_xor_sync(~0u, s, o);
    if (lane == 0) beta[row] = s;
}

// ------- fused select + exact-rescore + softmax + sparse gather -> G --------
// (round-12 proven version: full S~ scan, deterministic compaction)
#define MARGIN 22.0f
#define MAXC 512
__global__ __launch_bounds__(256)
void select_refine_gather(const __half* __restrict__ St,
                          const __half* __restrict__ Th, const __half* __restrict__ Tl,
                          const float* __restrict__ beta, const float* __restrict__ E,
                          __half* __restrict__ Gh)
{
    const size_t row = blockIdx.x;
    const int t = threadIdx.x, lane = t & 31, warp = t >> 5;

    __shared__ float tf[DIM];
    __shared__ float red[9];
    __shared__ int   wtot[8];
    __shared__ int   cols[MAXC];
    __shared__ float sc[MAXC];
    __shared__ int   Lsh;

    for (int i = t; i < DIM; i += 256)
        tf[i] = __half2float(Th[row * DIM + i]) + __half2float(Tl[row * DIM + i]);

    const uint4* srow = (const uint4*)(St + row * N_TOK);
    uint4 sv[4];
    float mx = -1e30f;
#pragma unroll
    for (int i = 0; i < 4; i++) {
        sv[i] = srow[i * 256 + t];
        const uint32_t* ww = (const uint32_t*)&sv[i];
#pragma unroll
        for (int w = 0; w < 4; w++) {
            const float2 f = __half22float2(*(const __half2*)&ww[w]);
            mx = fmaxf(mx, fmaxf(f.x, f.y));
        }
    }
#pragma unroll
    for (int o = 16; o > 0; o >>= 1) mx = fmaxf(mx, __shfl_xor_sync(~0u, mx, o));
    if (lane == 0) red[warp] = mx;
    __syncthreads();
    if (t == 0) { float m = red[0]; for (int w = 1; w < 8; w++) m = fmaxf(m, red[w]); red[8] = m; }
    __syncthreads();
    const float thr = red[8] - MARGIN;

    int cnt = 0;
#pragma unroll
    for (int i = 0; i < 4; i++) {
        const uint32_t* ww = (const uint32_t*)&sv[i];
#pragma unroll
        for (int w = 0; w < 4; w++) {
            const float2 f = __half22float2(*(const __half2*)&ww[w]);
            cnt += (f.x > thr) + (f.y > thr);
        }
    }
    int sc_in = cnt;
#pragma unroll
    for (int o = 1; o < 32; o <<= 1) {
        int n = __shfl_up_sync(~0u, sc_in, o);
        if (lane >= o) sc_in += n;
    }
    if (lane == 31) wtot[warp] = sc_in;
    __syncthreads();
    int wbase = 0, L = 0;
#pragma unroll
    for (int w = 0; w < 8; w++) { if (w < warp) wbase += wtot[w]; L += wtot[w]; }
    if (L > MAXC) L = MAXC;
    if (t == 0) Lsh = L;
    int pos = wbase + sc_in - cnt;
#pragma unroll
    for (int i = 0; i < 4; i++) {
        const uint32_t* ww = (const uint32_t*)&sv[i];
        const int cb = (i * 256 + t) * 8;
#pragma unroll
        for (int w = 0; w < 4; w++) {
            const float2 f = __half22float2(*(const __half2*)&ww[w]);
            if (f.x > thr) { if (pos < MAXC) cols[pos] = cb + w * 2;     pos++; }
            if (f.y > thr) { if (pos < MAXC) cols[pos] = cb + w * 2 + 1; pos++; }
        }
    }
    __syncthreads();
    L = Lsh;

    for (int ci = warp; ci < L; ci += 8) {
        const int j = cols[ci];
        const float* ej = E + (size_t)j * DIM;
        float s = 0.0f;
        for (int k = lane; k < DIM; k += 32) s += tf[k] * ej[k];
#pragma unroll
        for (int o = 16; o > 0; o >>= 1) s += __shfl_xor_sync(~0u, s, o);
        if (lane == 0) sc[ci] = s + beta[j];
    }
    __syncthreads();

    float m2 = -1e30f;
    for (int i = 0; i < L; i++) m2 = fmaxf(m2, sc[i]);
    float sum = 0.0f;
    for (int i = 0; i < L; i++) sum += __expf(sc[i] - m2);
    const float inv = 1.0f / sum;

    float4 acc = make_float4(0.f, 0.f, 0.f, 0.f);
    for (int i = 0; i < L; i++) {
        const float p = __expf(sc[i] - m2) * inv;
        const float4 e = ((const float4*)(E + (size_t)cols[i] * DIM))[t];
        acc.x += p * e.x; acc.y += p * e.y;
        acc.z += p * e.z; acc.w += p * e.w;
    }
    __half2 g0 = __halves2half2(__float2half(acc.x), __float2half(acc.y));
    __half2 g1 = __halves2half2(__float2half(acc.z), __float2half(acc.w));
    ((uint2*)(Gh + row * DIM))[t] = make_uint2(*(uint32_t*)&g0, *(uint32_t*)&g1);
}

// ----------------------------- launch --------------------------------------
extern "C" void kernel_launch(void* const* d_in, const int* in_sizes, int n_in,
                              void* d_out, int out_size)
{
    const float* emb = (const float*)d_in[0];
    const float* Wq  = (const float*)d_in[1];
    const float* bq  = (const float*)d_in[2];
    const float* Wk  = (const float*)d_in[3];
    const float* bk  = (const float*)d_in[4];   // cancels in softmax (row-const)
    const float* Wv  = (const float*)d_in[5];
    const float* bv  = (const float*)d_in[6];
    float* out = (float*)d_out;
    (void)bk;

    __half *eh, *el, *wqth, *wqtl, *wkth, *wktl, *wvh;
    __half *mth, *mtl, *th, *tl, *s16, *gh;
    float *mtp, *b2, *betav;
    cudaGetSymbolAddress((void**)&eh, g_eh);     cudaGetSymbolAddress((void**)&el, g_el);
    cudaGetSymbolAddress((void**)&wqth, g_wqth); cudaGetSymbolAddress((void**)&wqtl, g_wqtl);
    cudaGetSymbolAddress((void**)&wkth, g_wkth); cudaGetSymbolAddress((void**)&wktl, g_wktl);
    cudaGetSymbolAddress((void**)&wvh, g_wvh);
    cudaGetSymbolAddress((void**)&mtp, g_mtp);
    cudaGetSymbolAddress((void**)&mth, g_mth);   cudaGetSymbolAddress((void**)&mtl, g_mtl);
    cudaGetSymbolAddress((void**)&th, g_th);     cudaGetSymbolAddress((void**)&tl, g_tl);
    cudaGetSymbolAddress((void**)&b2, g_b2);     cudaGetSymbolAddress((void**)&betav, g_beta);
    cudaGetSymbolAddress((void**)&s16, g_s16);
    cudaGetSymbolAddress((void**)&gh, g_gh);

    static int once = 0;
    if (!once) {
        cudaFuncSetAttribute(gemm_w<3>, cudaFuncAttributeMaxDynamicSharedMemorySize, GSMEM);
        cudaFuncSetAttribute(gemm_w<1>, cudaFuncAttributeMaxDynamicSharedMemorySize, GSMEM);
        once = 1;
    }

    // preps
    split_f32<<<N_TOK * DIM / 4 / 256, 256>>>(emb, eh, el, N_TOK * DIM / 4);
    transpose_split2<<<dim3(DIM / 32, DIM / 32, 2), 256>>>(Wq, wqth, wqtl, Wk, wkth, wktl, DIM, DIM);
    split_f32<<<DIM * DIM / 4 / 256, 256>>>(Wv, wvh, nullptr, DIM * DIM / 4);
    bvec_k<<<DIM / 8, 256>>>(wkth, wktl, bq, b2);        // after transpose (dep ok)
    beta_k<<<N_TOK / 8, 256>>>(emb, b2, betav);

    // M^T = Wk^T @ Wq  (split-K z=4)
    gemm_w<3><<<dim3(DIM / 256, DIM / 128, 4), 256, GSMEM>>>(
        wkth, wktl, DIM, wqth, wqtl, DIM, nullptr, 0,
        mtp, nullptr, nullptr, DIM, DIM / 4, 0, (long long)DIM * DIM);
    reduce4_split<<<DIM * DIM / 256, 256>>>(mtp, mth, mtl, DIM * DIM);

    // T = E @ M  -> split hi/lo
    gemm_w<3><<<dim3(DIM / 256, N_TOK / 128), 256, GSMEM>>>(
        eh, el, DIM, mth, mtl, DIM, nullptr, 0,
        nullptr, th, tl, DIM, DIM, 1, 0);

    // approx scores: S~ = Th @ Eh^T + beta(col), 1-pass, fp16 out
    gemm_w<1><<<dim3(N_TOK / 256, N_TOK / 128), 256, GSMEM>>>(
        th, nullptr, DIM, eh, nullptr, DIM, betav, 1,
        nullptr, s16, nullptr, N_TOK, DIM, 2, 0);

    // select + exact rescore + softmax + sparse P*E -> G
    select_refine_gather<<<N_TOK, 256>>>(s16, th, tl, betav, emb, gh);

    // out = G @ Wv^T + bv  (1-pass)
    gemm_w<1><<<dim3(DIM / 256, N_TOK / 128), 256, GSMEM>>>(
        gh, nullptr, DIM, wvh, nullptr, DIM, bv, 1,
        out, nullptr, nullptr, DIM, DIM, 0, 0);
}